// round 12
// baseline (speedup 1.0000x reference)
#include <cuda_runtime.h>
#include <cstdint>

#define NE 256
#define NC 48
#define NB 64
#define NT 1024
#define ROWS 128
#define KT   32
#define PADW 36            // 36 % 32 == 4 -> conflict-free strided LDS
#define NTILES 512         // chunk-major: tile = chunk*64 + chain
#define BUF_FLOATS 6336    // fcw 48*36 + emb 128*36
#define SUB_FLOATS 12800   // 2 buffers + 128-int x_s per sub-worker
#define NCRF_BLOCKS 16     // 4 chains per block
#define GRID 148           // 1 block/SM forced by smem
#define SMEM_BYTES 153600  // 150KB -> 2/SM impossible (300 > 228) -> exclusive SMs

// contiguous sync state, zeroed by cudaMemsetAsync each replay:
// [0..512) tile flags, [512] tile counter, [513] done counter
static __device__ int   g_sync[514];
static __device__ float g_partial[NB];

// ---------- packed f32x2 helpers ----------
__device__ __forceinline__ unsigned long long ffma2(unsigned long long a, unsigned long long b,
                                                    unsigned long long c) {
    unsigned long long d;
    asm("fma.rn.f32x2 %0, %1, %2, %3;" : "=l"(d) : "l"(a), "l"(b), "l"(c));
    return d;
}
__device__ __forceinline__ unsigned long long fadd2(unsigned long long a, unsigned long long b) {
    unsigned long long d;
    asm("add.rn.f32x2 %0, %1, %2;" : "=l"(d) : "l"(a), "l"(b));
    return d;
}
__device__ __forceinline__ float2 unpack2(unsigned long long a) {
    float2 f;
    asm("mov.b64 {%0, %1}, %2;" : "=f"(f.x), "=f"(f.y) : "l"(a));
    return f;
}
__device__ __forceinline__ unsigned long long pack2(float x, float y) {
    unsigned long long d;
    asm("mov.b64 %0, {%1, %2};" : "=l"(d) : "f"(x), "f"(y));
    return d;
}
__device__ __forceinline__ float frcp_fast(float x) {
    float r; asm("rcp.approx.f32 %0, %1;" : "=f"(r) : "f"(x)); return r;
}
__device__ __forceinline__ uint32_t smem_u32(const void* p) {
    uint32_t a;
    asm("{ .reg .u64 t; cvta.to.shared.u64 t, %1; cvt.u32.u64 %0, t; }" : "=r"(a) : "l"(p));
    return a;
}
__device__ __forceinline__ void ldgsts16(uint32_t dst, const void* src) {
    asm volatile("cp.async.cg.shared.global [%0], [%1], 16;" :: "r"(dst), "l"(src));
}
__device__ __forceinline__ void barsync(int id, int cnt) {
    asm volatile("bar.sync %0, %1;" :: "r"(id), "r"(cnt) : "memory");
}

// ============================================================================
// Fused kernel: 148 blocks x 384 threads, 150KB smem -> 1 block/SM.
//  blocks [0,16):    CRF — 4 chains/block (bars 1-4), 64 threads each.
//  blocks [16,148):  GEMM — 3 independent 128-thread sub-workers (bars 1-3),
//                    R9-proven 8x6 cp.async pipeline, chunk-major tile pull.
// ============================================================================
__global__ __launch_bounds__(384, 1) void fused_kernel(
    const int* __restrict__ x, const int* __restrict__ labels,
    const float* __restrict__ emb, const float* __restrict__ fcw,
    const float* __restrict__ fcb, const float* __restrict__ start_trans,
    const float* __restrict__ end_trans, const float* __restrict__ trans,
    float* __restrict__ out, int out_size)
{
    extern __shared__ float sm[];
    __shared__ int t_sh[3];
    const int tid = threadIdx.x;

    if (blockIdx.x >= NCRF_BLOCKS) {
        // ==================== GEMM: sub-worker w of 3 ====================
        const int w     = tid >> 7;        // 0..2
        const int wtid  = tid & 127;
        const int barid = 1 + w;

        float* base_f = sm + w * SUB_FLOATS;
        int*   x_s    = (int*)(base_f + 2 * BUF_FLOATS);
        const uint32_t smbase = smem_u32(base_f);

        const int tx = wtid & 7;    // col group 0..7
        const int ty = wtid >> 3;   // row group 0..15

        for (;;) {
            if (wtid == 0) t_sh[w] = atomicAdd(&g_sync[512], 1);
            barsync(barid, 128);
            const int tile = t_sh[w];
            if (tile >= NTILES) break;

            const int chain   = tile & 63;
            const int chunk   = tile >> 6;
            const int rowBase = chain * NT + chunk * ROWS;

            x_s[wtid] = x[rowBase + wtid];
            barsync(barid, 128);

            #define LOAD_TILE(KIDX, BUF)                                           \
            {                                                                      \
                const int k0 = (KIDX) * KT;                                        \
                const uint32_t fb  = smbase + (BUF) * BUF_FLOATS * 4;              \
                const uint32_t ebs = fb + 1728 * 4;                                \
                for (int i = wtid; i < 384; i += 128) {                            \
                    int r = i >> 3, k4 = i & 7;                                    \
                    ldgsts16(fb + (r * PADW + 4 * k4) * 4,                         \
                             fcw + r * NE + k0 + 4 * k4);                          \
                }                                                                  \
                for (int i = wtid; i < 1024; i += 128) {                           \
                    int r = i >> 3, k4 = i & 7;                                    \
                    ldgsts16(ebs + (r * PADW + 4 * k4) * 4,                        \
                             emb + (size_t)x_s[r] * NE + k0 + 4 * k4);             \
                }                                                                  \
                asm volatile("cp.async.commit_group;");                            \
            }

            LOAD_TILE(0, 0);

            unsigned long long acc[8][6];
            #pragma unroll
            for (int m = 0; m < 8; m++)
                #pragma unroll
                for (int n = 0; n < 6; n++) acc[m][n] = 0ull;

            for (int kt = 0; kt < 8; kt++) {
                if (kt < 7) {
                    LOAD_TILE(kt + 1, (kt + 1) & 1);
                    asm volatile("cp.async.wait_group %0;" :: "n"(1));
                } else {
                    asm volatile("cp.async.wait_group %0;" :: "n"(0));
                }
                barsync(barid, 128);

                const float* fcw_s = base_f + (kt & 1) * BUF_FLOATS;
                const float* emb_s = fcw_s + 1728;

                #pragma unroll 2
                for (int k2 = 0; k2 < KT / 2; k2++) {
                    unsigned long long a2[8], w2[6];
                    #pragma unroll
                    for (int m = 0; m < 8; m++)
                        a2[m] = *(const unsigned long long*)&emb_s[(ty + 16 * m) * PADW + 2 * k2];
                    #pragma unroll
                    for (int n = 0; n < 6; n++)
                        w2[n] = *(const unsigned long long*)&fcw_s[(tx + 8 * n) * PADW + 2 * k2];
                    #pragma unroll
                    for (int m = 0; m < 8; m++)
                        #pragma unroll
                        for (int n = 0; n < 6; n++)
                            acc[m][n] = ffma2(a2[m], w2[n], acc[m][n]);
                }
                barsync(barid, 128);
            }
            #undef LOAD_TILE

            #pragma unroll
            for (int m = 0; m < 8; m++) {
                int r = rowBase + ty + 16 * m;
                #pragma unroll
                for (int n = 0; n < 6; n++) {
                    int c = tx + 8 * n;
                    float2 p = unpack2(acc[m][n]);
                    out[(size_t)r * NC + c] = p.x + p.y + __ldg(&fcb[c]);
                }
            }
            __threadfence();
            barsync(barid, 128);
            if (wtid == 0) atomicExch(&g_sync[tile], 1);
        }
        return;
    }

    // ==================== CRF: 4 chains per block ====================
    if (tid >= 256) return;

    const int q     = tid >> 6;            // chain within block 0..3
    const int ct    = tid & 63;            // chain-local tid
    const int b     = blockIdx.x * 4 + q;
    const int barid = 1 + q;

    float* chsm = sm + q * 192;
    float (*a_sh)[64] = (float(*)[64])chsm;   // [2][64]
    float* red = chsm + 128;                  // [64]

    const float* lg  = out    + (size_t)b * NT * NC;
    const int*   lab = labels + b * NT;

    #define WAIT_CHUNK(NEED)                                                   \
    {                                                                          \
        if (ct == 0) {                                                         \
            volatile int* f = &g_sync[(NEED) * 64 + b];                        \
            while (*f == 0) __nanosleep(64);                                   \
            __threadfence();                                                   \
        }                                                                      \
        barsync(barid, 64);                                                    \
    }

    const int cc = (ct < NC) ? ct : (NC - 1);

    unsigned long long Ec2[24];
    #pragma unroll
    for (int j = 0; j < 24; j++) {
        float e0 = __expf(trans[(2 * j)     * NC + cc]) * 0.015625f;  // /64
        float e1 = __expf(trans[(2 * j + 1) * NC + cc]) * 0.015625f;
        Ec2[j] = pack2(e0, e1);
    }

    WAIT_CHUNK(0);
    float a_cur = __expf(start_trans[cc] + lg[cc]);
    a_sh[0][ct] = a_cur;

    float logscale = 0.f;
    float eb[4];
    #pragma unroll
    for (int jj = 0; jj < 4; jj++) eb[jj] = lg[(1 + jj) * NC + cc];
    barsync(barid, 64);

    int p = 0;
    int ready = 0;

    // lean step: no renorm machinery in the loop body
    #define CRF_STEP(EMIS)                                                     \
    {                                                                          \
        float ex = __expf(EMIS);                                               \
        unsigned long long s0 = 0ull, s1 = 0ull, s2 = 0ull, s3 = 0ull;         \
        _Pragma("unroll")                                                      \
        for (int j = 0; j < 12; j += 2) {                                      \
            ulonglong2 u = *(const ulonglong2*)&a_sh[p][4 * j];                \
            ulonglong2 v = *(const ulonglong2*)&a_sh[p][4 * j + 4];            \
            s0 = ffma2(u.x, Ec2[2 * j],     s0);                               \
            s1 = ffma2(u.y, Ec2[2 * j + 1], s1);                               \
            s2 = ffma2(v.x, Ec2[2 * j + 2], s2);                               \
            s3 = ffma2(v.y, Ec2[2 * j + 3], s3);                               \
        }                                                                      \
        float2 sp = unpack2(fadd2(fadd2(s0, s2), fadd2(s1, s3)));              \
        float anew = (sp.x + sp.y) * ex;                                       \
        a_sh[p ^ 1][ct] = anew;                                                \
        a_cur = anew;                                                          \
        barsync(barid, 64);                                                    \
        p ^= 1;                                                                \
    }

    // 255 groups of 4 steps (t = 1..1020); uniform renorm branch per 32 groups
    for (int g = 0; g < 255; g++) {
        const int tb = 4 * g + 1;
        int need = (tb + 7) >> 7;
        need = (need > 7) ? 7 : need;
        if (need > ready) { WAIT_CHUNK(need); ready = need; }

        float en[4];
        #pragma unroll
        for (int jj = 0; jj < 4; jj++) {
            int tt = tb + 4 + jj;
            tt = (tt < NT) ? tt : (NT - 1);
            en[jj] = lg[tt * NC + cc];
        }
        CRF_STEP(eb[0]);
        CRF_STEP(eb[1]);
        CRF_STEP(eb[2]);
        CRF_STEP(eb[3]);
        eb[0] = en[0]; eb[1] = en[1]; eb[2] = en[2]; eb[3] = en[3];

        if ((g & 31) == 31) {               // after t = 128,256,...,896 (g<=223)
            float r = a_sh[p][0];           // all threads read slot 0
            barsync(barid, 64);             // ... before it is overwritten
            a_cur *= frcp_fast(r);
            a_sh[p][ct] = a_cur;
            logscale += __logf(r);          // identical in every thread
            barsync(barid, 64);
        }
    }
    // epilogue: t = 1021, 1022, 1023
    CRF_STEP(eb[0]);
    CRF_STEP(eb[1]);
    CRF_STEP(eb[2]);
    #undef CRF_STEP
    #undef WAIT_CHUNK

    // ---- logZ partial ----
    if (ct < NC) red[ct] = a_cur * __expf(end_trans[ct]);
    barsync(barid, 64);
    float logz_part = 0.f;
    if (ct == 0) {
        float s = 0.f;
        #pragma unroll
        for (int i = 0; i < NC; i++) s += red[i];
        logz_part = __logf(s) + logscale + 4254.5374f;   // + 1023*ln(64)
    }
    barsync(barid, 64);

    // ---- numerator (own chunks all ready), fixed-order reduce ----
    float acc = 0.f;
    for (int t = ct; t < NT; t += 64) {
        int lt = lab[t];
        acc += lg[t * NC + lt];
        if (t + 1 < NT) acc += trans[lt * NC + lab[t + 1]];
    }
    if (ct == 0)  acc += start_trans[lab[0]];
    if (ct == 63) acc += end_trans[lab[NT - 1]];
    red[ct] = acc;
    barsync(barid, 64);
    if (ct == 0) {
        float num = 0.f;
        #pragma unroll
        for (int i = 0; i < 64; i++) num += red[i];
        g_partial[b] = num - logz_part;
        __threadfence();
        int v = atomicAdd(&g_sync[513], 1);
        if (v == NB - 1) {                 // last chain writes -llh
            float tot = 0.f;
            #pragma unroll
            for (int i = 0; i < NB; i++) tot += g_partial[i];
            out[out_size - 1] = -tot;
        }
    }
}

extern "C" void kernel_launch(void* const* d_in, const int* in_sizes, int n_in,
                              void* d_out, int out_size)
{
    const int*   x    = (const int*)  d_in[0];
    const int*   lab  = (const int*)  d_in[1];
    const float* emb  = (const float*)d_in[2];
    const float* fcw  = (const float*)d_in[3];
    const float* fcb  = (const float*)d_in[4];
    const float* st   = (const float*)d_in[5];
    const float* et   = (const float*)d_in[6];
    const float* tr   = (const float*)d_in[7];
    float* out = (float*)d_out;

    void* syncAddr = nullptr;
    cudaGetSymbolAddress(&syncAddr, g_sync);
    cudaMemsetAsync(syncAddr, 0, sizeof(int) * 514);

    cudaFuncSetAttribute(fused_kernel, cudaFuncAttributeMaxDynamicSharedMemorySize, SMEM_BYTES);
    fused_kernel<<<GRID, 384, SMEM_BYTES>>>(x, lab, emb, fcw, fcb, st, et, tr, out, out_size);
}

// round 13
// speedup vs baseline: 1.2706x; 1.2706x over previous
#include <cuda_runtime.h>
#include <cstdint>

#define NE 256
#define NC 48
#define NB 64
#define NT 1024
#define ROWS 128
#define KT   32
#define PADW 36            // 36 % 32 == 4 -> conflict-free strided LDS
#define NTILES 512         // chunk-major: tile = chunk*64 + chain
#define BUF_FLOATS 6336    // fcw 48*36 + emb 128*36
#define SUB_FLOATS 12800   // 2 buffers + 128-int x_s per sub-worker
#define NCRF_BLOCKS 32     // 2 chains per block
#define GRID 148           // 1 block/SM forced by smem
#define SMEM_BYTES 153600  // 150KB -> 2/SM impossible -> exclusive SMs

// contiguous sync state, zeroed by cudaMemsetAsync each replay:
// [0..512) tile flags, [512] tile counter, [513] done counter
static __device__ int   g_sync[514];
static __device__ float g_partial[NB];

// ---------- packed f32x2 helpers ----------
__device__ __forceinline__ unsigned long long ffma2(unsigned long long a, unsigned long long b,
                                                    unsigned long long c) {
    unsigned long long d;
    asm("fma.rn.f32x2 %0, %1, %2, %3;" : "=l"(d) : "l"(a), "l"(b), "l"(c));
    return d;
}
__device__ __forceinline__ unsigned long long fadd2(unsigned long long a, unsigned long long b) {
    unsigned long long d;
    asm("add.rn.f32x2 %0, %1, %2;" : "=l"(d) : "l"(a), "l"(b));
    return d;
}
__device__ __forceinline__ float2 unpack2(unsigned long long a) {
    float2 f;
    asm("mov.b64 {%0, %1}, %2;" : "=f"(f.x), "=f"(f.y) : "l"(a));
    return f;
}
__device__ __forceinline__ unsigned long long pack2(float x, float y) {
    unsigned long long d;
    asm("mov.b64 %0, {%1, %2};" : "=l"(d) : "f"(x), "f"(y));
    return d;
}
__device__ __forceinline__ float frcp_fast(float x) {
    float r; asm("rcp.approx.f32 %0, %1;" : "=f"(r) : "f"(x)); return r;
}
__device__ __forceinline__ uint32_t smem_u32(const void* p) {
    uint32_t a;
    asm("{ .reg .u64 t; cvta.to.shared.u64 t, %1; cvt.u32.u64 %0, t; }" : "=r"(a) : "l"(p));
    return a;
}
__device__ __forceinline__ void ldgsts16(uint32_t dst, const void* src) {
    asm volatile("cp.async.cg.shared.global [%0], [%1], 16;" :: "r"(dst), "l"(src));
}
__device__ __forceinline__ void barsync(int id, int cnt) {
    asm volatile("bar.sync %0, %1;" :: "r"(id), "r"(cnt) : "memory");
}

// ============================================================================
// Fused kernel: 148 blocks x 384 threads, 150KB smem -> 1 block/SM.
//  blocks [0,32):    CRF — 2 chains/block (bars 1,2), 64 threads each,
//                    R7-proven FLAT scan loop (NOT the chunked R12 shape).
//  blocks [32,148):  GEMM — 3 independent 128-thread sub-workers (bars 1-3),
//                    R9-proven 8x6 cp.async pipeline, chunk-major tile pull.
// ============================================================================
__global__ __launch_bounds__(384, 1) void fused_kernel(
    const int* __restrict__ x, const int* __restrict__ labels,
    const float* __restrict__ emb, const float* __restrict__ fcw,
    const float* __restrict__ fcb, const float* __restrict__ start_trans,
    const float* __restrict__ end_trans, const float* __restrict__ trans,
    float* __restrict__ out, int out_size)
{
    extern __shared__ float sm[];
    __shared__ int t_sh[3];
    const int tid = threadIdx.x;

    if (blockIdx.x >= NCRF_BLOCKS) {
        // ==================== GEMM: sub-worker w of 3 ====================
        const int w     = tid >> 7;        // 0..2
        const int wtid  = tid & 127;
        const int barid = 1 + w;

        float* base_f = sm + w * SUB_FLOATS;
        int*   x_s    = (int*)(base_f + 2 * BUF_FLOATS);
        const uint32_t smbase = smem_u32(base_f);

        const int tx = wtid & 7;    // col group 0..7
        const int ty = wtid >> 3;   // row group 0..15

        for (;;) {
            if (wtid == 0) t_sh[w] = atomicAdd(&g_sync[512], 1);
            barsync(barid, 128);
            const int tile = t_sh[w];
            if (tile >= NTILES) break;

            const int chain   = tile & 63;
            const int chunk   = tile >> 6;
            const int rowBase = chain * NT + chunk * ROWS;

            x_s[wtid] = x[rowBase + wtid];
            barsync(barid, 128);

            #define LOAD_TILE(KIDX, BUF)                                           \
            {                                                                      \
                const int k0 = (KIDX) * KT;                                        \
                const uint32_t fb  = smbase + (BUF) * BUF_FLOATS * 4;              \
                const uint32_t ebs = fb + 1728 * 4;                                \
                for (int i = wtid; i < 384; i += 128) {                            \
                    int r = i >> 3, k4 = i & 7;                                    \
                    ldgsts16(fb + (r * PADW + 4 * k4) * 4,                         \
                             fcw + r * NE + k0 + 4 * k4);                          \
                }                                                                  \
                for (int i = wtid; i < 1024; i += 128) {                           \
                    int r = i >> 3, k4 = i & 7;                                    \
                    ldgsts16(ebs + (r * PADW + 4 * k4) * 4,                        \
                             emb + (size_t)x_s[r] * NE + k0 + 4 * k4);             \
                }                                                                  \
                asm volatile("cp.async.commit_group;");                            \
            }

            LOAD_TILE(0, 0);

            unsigned long long acc[8][6];
            #pragma unroll
            for (int m = 0; m < 8; m++)
                #pragma unroll
                for (int n = 0; n < 6; n++) acc[m][n] = 0ull;

            for (int kt = 0; kt < 8; kt++) {
                if (kt < 7) {
                    LOAD_TILE(kt + 1, (kt + 1) & 1);
                    asm volatile("cp.async.wait_group %0;" :: "n"(1));
                } else {
                    asm volatile("cp.async.wait_group %0;" :: "n"(0));
                }
                barsync(barid, 128);

                const float* fcw_s = base_f + (kt & 1) * BUF_FLOATS;
                const float* emb_s = fcw_s + 1728;

                #pragma unroll 2
                for (int k2 = 0; k2 < KT / 2; k2++) {
                    unsigned long long a2[8], w2[6];
                    #pragma unroll
                    for (int m = 0; m < 8; m++)
                        a2[m] = *(const unsigned long long*)&emb_s[(ty + 16 * m) * PADW + 2 * k2];
                    #pragma unroll
                    for (int n = 0; n < 6; n++)
                        w2[n] = *(const unsigned long long*)&fcw_s[(tx + 8 * n) * PADW + 2 * k2];
                    #pragma unroll
                    for (int m = 0; m < 8; m++)
                        #pragma unroll
                        for (int n = 0; n < 6; n++)
                            acc[m][n] = ffma2(a2[m], w2[n], acc[m][n]);
                }
                barsync(barid, 128);
            }
            #undef LOAD_TILE

            #pragma unroll
            for (int m = 0; m < 8; m++) {
                int r = rowBase + ty + 16 * m;
                #pragma unroll
                for (int n = 0; n < 6; n++) {
                    int c = tx + 8 * n;
                    float2 p = unpack2(acc[m][n]);
                    out[(size_t)r * NC + c] = p.x + p.y + __ldg(&fcb[c]);
                }
            }
            __threadfence();
            barsync(barid, 128);
            if (wtid == 0) atomicExch(&g_sync[tile], 1);
        }
        return;
    }

    // ==================== CRF: 2 chains per block, FLAT loop ====================
    if (tid >= 128) return;

    const int half  = tid >> 6;            // chain within block
    const int ct    = tid & 63;            // chain-local tid
    const int b     = blockIdx.x * 2 + half;
    const int barid = 1 + half;

    float* chsm = sm + half * 192;
    float (*a_sh)[64] = (float(*)[64])chsm;   // [2][64]
    float* red = chsm + 128;                  // [64]

    const float* lg  = out    + (size_t)b * NT * NC;
    const int*   lab = labels + b * NT;

    #define WAIT_CHUNK(NEED)                                                   \
    {                                                                          \
        if (ct == 0) {                                                         \
            volatile int* f = &g_sync[(NEED) * 64 + b];                        \
            while (*f == 0) __nanosleep(64);                                   \
            __threadfence();                                                   \
        }                                                                      \
        barsync(barid, 64);                                                    \
    }

    const int cc = (ct < NC) ? ct : (NC - 1);

    unsigned long long Ec2[24];
    #pragma unroll
    for (int j = 0; j < 24; j++) {
        float e0 = __expf(trans[(2 * j)     * NC + cc]) * 0.015625f;  // /64
        float e1 = __expf(trans[(2 * j + 1) * NC + cc]) * 0.015625f;
        Ec2[j] = pack2(e0, e1);
    }

    WAIT_CHUNK(0);
    float a_cur = __expf(start_trans[cc] + lg[cc]);
    a_sh[0][ct] = a_cur;

    float logscale = 0.f;
    float eb[4];
    #pragma unroll
    for (int jj = 0; jj < 4; jj++) eb[jj] = lg[(1 + jj) * NC + cc];
    barsync(barid, 64);

    int p = 0;
    int ready = 0;

    #define CRF_STEP(T, EMIS)                                                  \
    {                                                                          \
        float ex = __expf(EMIS);                                               \
        float r  = a_sh[p][0];                                                 \
        unsigned long long s0 = 0ull, s1 = 0ull, s2 = 0ull, s3 = 0ull;         \
        _Pragma("unroll")                                                      \
        for (int j = 0; j < 12; j += 2) {                                      \
            ulonglong2 u = *(const ulonglong2*)&a_sh[p][4 * j];                \
            ulonglong2 v = *(const ulonglong2*)&a_sh[p][4 * j + 4];            \
            s0 = ffma2(u.x, Ec2[2 * j],     s0);                               \
            s1 = ffma2(u.y, Ec2[2 * j + 1], s1);                               \
            s2 = ffma2(v.x, Ec2[2 * j + 2], s2);                               \
            s3 = ffma2(v.y, Ec2[2 * j + 3], s3);                               \
        }                                                                      \
        float2 sp = unpack2(fadd2(fadd2(s0, s2), fadd2(s1, s3)));              \
        float s = sp.x + sp.y;                                                 \
        bool rn = ((T) & 127) == 0;                                            \
        float sel = rn ? frcp_fast(r) : 1.0f;                                  \
        logscale += rn ? __logf(r) : 0.0f;                                     \
        float anew = s * ex * sel;                                             \
        a_sh[p ^ 1][ct] = anew;                                                \
        a_cur = anew;                                                          \
        barsync(barid, 64);                                                    \
        p ^= 1;                                                                \
    }

    for (int tb = 1; tb + 3 < NT; tb += 4) {
        int need = (tb + 7) >> 7;
        need = (need > 7) ? 7 : need;
        if (need > ready) { WAIT_CHUNK(need); ready = need; }

        float en[4];
        #pragma unroll
        for (int jj = 0; jj < 4; jj++) {
            int tt = tb + 4 + jj;
            tt = (tt < NT) ? tt : (NT - 1);
            en[jj] = lg[tt * NC + cc];
        }
        CRF_STEP(tb + 0, eb[0]);
        CRF_STEP(tb + 1, eb[1]);
        CRF_STEP(tb + 2, eb[2]);
        CRF_STEP(tb + 3, eb[3]);
        eb[0] = en[0]; eb[1] = en[1]; eb[2] = en[2]; eb[3] = en[3];
    }
    CRF_STEP(NT - 3, eb[0]);
    CRF_STEP(NT - 2, eb[1]);
    CRF_STEP(NT - 1, eb[2]);
    #undef CRF_STEP
    #undef WAIT_CHUNK

    // ---- logZ partial ----
    if (ct < NC) red[ct] = a_cur * __expf(end_trans[ct]);
    barsync(barid, 64);
    float logz_part = 0.f;
    if (ct == 0) {
        float s = 0.f;
        #pragma unroll
        for (int i = 0; i < NC; i++) s += red[i];
        logz_part = __logf(s) + logscale + 4254.5374f;   // + 1023*ln(64)
    }
    barsync(barid, 64);

    // ---- numerator (own chunks all ready), fixed-order reduce ----
    float acc = 0.f;
    for (int t = ct; t < NT; t += 64) {
        int lt = lab[t];
        acc += lg[t * NC + lt];
        if (t + 1 < NT) acc += trans[lt * NC + lab[t + 1]];
    }
    if (ct == 0)  acc += start_trans[lab[0]];
    if (ct == 63) acc += end_trans[lab[NT - 1]];
    red[ct] = acc;
    barsync(barid, 64);
    if (ct == 0) {
        float num = 0.f;
        #pragma unroll
        for (int i = 0; i < 64; i++) num += red[i];
        g_partial[b] = num - logz_part;
        __threadfence();
        int v = atomicAdd(&g_sync[513], 1);
        if (v == NB - 1) {                 // last chain writes -llh
            float tot = 0.f;
            #pragma unroll
            for (int i = 0; i < NB; i++) tot += g_partial[i];
            out[out_size - 1] = -tot;
        }
    }
}

extern "C" void kernel_launch(void* const* d_in, const int* in_sizes, int n_in,
                              void* d_out, int out_size)
{
    const int*   x    = (const int*)  d_in[0];
    const int*   lab  = (const int*)  d_in[1];
    const float* emb  = (const float*)d_in[2];
    const float* fcw  = (const float*)d_in[3];
    const float* fcb  = (const float*)d_in[4];
    const float* st   = (const float*)d_in[5];
    const float* et   = (const float*)d_in[6];
    const float* tr   = (const float*)d_in[7];
    float* out = (float*)d_out;

    void* syncAddr = nullptr;
    cudaGetSymbolAddress(&syncAddr, g_sync);
    cudaMemsetAsync(syncAddr, 0, sizeof(int) * 514);

    cudaFuncSetAttribute(fused_kernel, cudaFuncAttributeMaxDynamicSharedMemorySize, SMEM_BYTES);
    fused_kernel<<<GRID, 384, SMEM_BYTES>>>(x, lab, emb, fcw, fcb, st, et, tr, out, out_size);
}

// round 14
// speedup vs baseline: 1.6020x; 1.2608x over previous
#include <cuda_runtime.h>
#include <cstdint>

#define NE 256
#define NC 48
#define NB 64
#define NT 1024
#define MROWS 64          // GEMM M-tile (4 warps x 16)
#define KT   64           // K-tile (floats)
#define PADK 68           // padded row stride: %32==4 -> conflict-free
#define BFLO (NC * PADK)            // 3264 floats: B tile
#define AFLO (MROWS * PADK)         // 4352 floats: A tile
#define TILE_FLOATS (BFLO + AFLO)   // 7616
#define GEMM_SMEM (2 * TILE_FLOATS * 4 + MROWS * 4)   // 61184 B
#define NBLK (NB * NT / MROWS)      // 1024 blocks

static __device__ float g_partial[NB];
static __device__ int   g_done;     // zero-init; self-resets each run

// ---------- helpers ----------
__device__ __forceinline__ unsigned long long ffma2(unsigned long long a, unsigned long long b,
                                                    unsigned long long c) {
    unsigned long long d;
    asm("fma.rn.f32x2 %0, %1, %2, %3;" : "=l"(d) : "l"(a), "l"(b), "l"(c));
    return d;
}
__device__ __forceinline__ unsigned long long fadd2(unsigned long long a, unsigned long long b) {
    unsigned long long d;
    asm("add.rn.f32x2 %0, %1, %2;" : "=l"(d) : "l"(a), "l"(b));
    return d;
}
__device__ __forceinline__ float2 unpack2(unsigned long long a) {
    float2 f;
    asm("mov.b64 {%0, %1}, %2;" : "=f"(f.x), "=f"(f.y) : "l"(a));
    return f;
}
__device__ __forceinline__ unsigned long long pack2(float x, float y) {
    unsigned long long d;
    asm("mov.b64 %0, {%1, %2};" : "=l"(d) : "f"(x), "f"(y));
    return d;
}
__device__ __forceinline__ float frcp_fast(float x) {
    float r; asm("rcp.approx.f32 %0, %1;" : "=f"(r) : "f"(x)); return r;
}
__device__ __forceinline__ uint32_t smem_u32(const void* p) {
    uint32_t a;
    asm("{ .reg .u64 t; cvta.to.shared.u64 t, %1; cvt.u32.u64 %0, t; }" : "=r"(a) : "l"(p));
    return a;
}
__device__ __forceinline__ void ldgsts16(uint32_t dst, const void* src) {
    asm volatile("cp.async.cg.shared.global [%0], [%1], 16;" :: "r"(dst), "l"(src));
}
__device__ __forceinline__ uint32_t f2tf32(float x) {
    uint32_t r; asm("cvt.rna.tf32.f32 %0, %1;" : "=r"(r) : "f"(x)); return r;
}
__device__ __forceinline__ void mma_tf32(float& d0, float& d1, float& d2, float& d3,
                                         uint32_t a0, uint32_t a1, uint32_t a2, uint32_t a3,
                                         uint32_t b0, uint32_t b1) {
    asm volatile(
        "mma.sync.aligned.m16n8k8.row.col.f32.tf32.tf32.f32 "
        "{%0,%1,%2,%3}, {%4,%5,%6,%7}, {%8,%9}, {%0,%1,%2,%3};"
        : "+f"(d0), "+f"(d1), "+f"(d2), "+f"(d3)
        : "r"(a0), "r"(a1), "r"(a2), "r"(a3), "r"(b0), "r"(b1));
}

// ============================================================================
// Kernel 1: logits = gather(emb)[65536x256] @ fc_w^T[48x256] + fc_b
// tf32 tensor path: 128 threads (4 warps), M-tile 64 (16/warp), N=48 (6 mma
// n-tiles), K in 4 cp.async double-buffered tiles of 64. Fragments loaded
// with the m16n8k8 thread maps from PADK=68 smem (bank-perfect).
// ============================================================================
__global__ __launch_bounds__(128, 3) void gemm_kernel(
    const int* __restrict__ x, const float* __restrict__ emb,
    const float* __restrict__ fcw, const float* __restrict__ fcb,
    float* __restrict__ out)
{
    extern __shared__ float sm[];
    int* x_s = (int*)(sm + 2 * TILE_FLOATS);

    const int tid  = threadIdx.x;
    const int w    = tid >> 5;        // warp 0..3
    const int lane = tid & 31;
    const int qr   = lane >> 2;       // 0..7
    const int qc   = lane & 3;        // 0..3
    const int rowBase = blockIdx.x * MROWS;

    if (tid < MROWS) x_s[tid] = x[rowBase + tid];
    __syncthreads();

    const uint32_t smbase = smem_u32(sm);

    // K-tile: B = fcw[48 x 64] then A = gathered emb[64 x 64], both PADK rows
    #define LOAD_TILE(KIDX, BUF)                                               \
    {                                                                          \
        const int k0 = (KIDX) * KT;                                            \
        const uint32_t bb = smbase + (BUF) * TILE_FLOATS * 4;                  \
        const uint32_t ab = bb + BFLO * 4;                                     \
        for (int i = tid; i < 768; i += 128) {       /* B: 48 x 16 float4 */   \
            int n = i >> 4, k4 = i & 15;                                       \
            ldgsts16(bb + (n * PADK + 4 * k4) * 4,                             \
                     fcw + n * NE + k0 + 4 * k4);                              \
        }                                                                      \
        for (int i = tid; i < 1024; i += 128) {      /* A: 64 x 16 float4 */   \
            int r = i >> 4, k4 = i & 15;                                       \
            ldgsts16(ab + (r * PADK + 4 * k4) * 4,                             \
                     emb + (size_t)x_s[r] * NE + k0 + 4 * k4);                 \
        }                                                                      \
        asm volatile("cp.async.commit_group;");                                \
    }

    LOAD_TILE(0, 0);

    float acc[6][4];
    #pragma unroll
    for (int nt = 0; nt < 6; nt++)
        #pragma unroll
        for (int i = 0; i < 4; i++) acc[nt][i] = 0.f;

    for (int kt = 0; kt < 4; kt++) {
        if (kt < 3) {
            LOAD_TILE(kt + 1, (kt + 1) & 1);
            asm volatile("cp.async.wait_group %0;" :: "n"(1));
        } else {
            asm volatile("cp.async.wait_group %0;" :: "n"(0));
        }
        __syncthreads();

        const float* Bs = sm + (kt & 1) * TILE_FLOATS;
        const float* As = Bs + BFLO;
        const int rowA = 16 * w + qr;

        #pragma unroll
        for (int k8 = 0; k8 < 8; k8++) {
            const int kb = k8 * 8 + qc;
            uint32_t a0 = f2tf32(As[rowA * PADK + kb]);
            uint32_t a1 = f2tf32(As[(rowA + 8) * PADK + kb]);
            uint32_t a2 = f2tf32(As[rowA * PADK + kb + 4]);
            uint32_t a3 = f2tf32(As[(rowA + 8) * PADK + kb + 4]);
            #pragma unroll
            for (int nt = 0; nt < 6; nt++) {
                uint32_t b0 = f2tf32(Bs[(nt * 8 + qr) * PADK + kb]);
                uint32_t b1 = f2tf32(Bs[(nt * 8 + qr) * PADK + kb + 4]);
                mma_tf32(acc[nt][0], acc[nt][1], acc[nt][2], acc[nt][3],
                         a0, a1, a2, a3, b0, b1);
            }
        }
        __syncthreads();
    }
    #undef LOAD_TILE

    // epilogue: c0 -> (qr, 2qc), c1 -> (qr, 2qc+1), c2/c3 -> row+8
    const int gr = rowBase + 16 * w + qr;
    #pragma unroll
    for (int nt = 0; nt < 6; nt++) {
        const int c = nt * 8 + 2 * qc;
        out[(size_t)gr * NC + c]            = acc[nt][0] + __ldg(&fcb[c]);
        out[(size_t)gr * NC + c + 1]        = acc[nt][1] + __ldg(&fcb[c + 1]);
        out[(size_t)(gr + 8) * NC + c]      = acc[nt][2] + __ldg(&fcb[c]);
        out[(size_t)(gr + 8) * NC + c + 1]  = acc[nt][3] + __ldg(&fcb[c + 1]);
    }
}

// ============================================================================
// Kernel 2: CRF forward scan — R7 structure verbatim (best measured).
// 64 threads/block, flat 4-step-unrolled loop, in-step branchless renorm,
// in-loop __expf, 4-step emission prefetch. Fused last-block final reduce.
// ============================================================================
__global__ __launch_bounds__(64) void crf_kernel(
    const float* __restrict__ logits,
    const int* __restrict__ labels,
    const float* __restrict__ start_trans,
    const float* __restrict__ end_trans,
    const float* __restrict__ trans,
    float* __restrict__ out, int out_size)
{
    __shared__ __align__(16) float a_sh[2][64];
    __shared__ float red[64];

    const int b   = blockIdx.x;
    const int tid = threadIdx.x;
    const float* lg  = logits + (size_t)b * NT * NC;
    const int*   lab = labels + b * NT;

    // ---- numerator (parallel over t, fixed-order reduce) ----
    float acc = 0.f;
    for (int t = tid; t < NT; t += 64) {
        int lt = lab[t];
        acc += lg[t * NC + lt];
        if (t + 1 < NT) acc += trans[lt * NC + lab[t + 1]];
    }
    if (tid == 0)  acc += start_trans[lab[0]];
    if (tid == 63) acc += end_trans[lab[NT - 1]];
    red[tid] = acc;
    __syncthreads();
    float num = 0.f;
    if (tid == 0) {
        #pragma unroll
        for (int i = 0; i < 64; i++) num += red[i];
    }

    // ---- branch-free setup ----
    const int cc = (tid < NC) ? tid : (NC - 1);

    unsigned long long Ec2[24];
    #pragma unroll
    for (int j = 0; j < 24; j++) {
        float e0 = __expf(trans[(2 * j)     * NC + cc]) * 0.015625f;  // /64
        float e1 = __expf(trans[(2 * j + 1) * NC + cc]) * 0.015625f;
        Ec2[j] = pack2(e0, e1);
    }
    float a_cur = __expf(start_trans[cc] + lg[cc]);
    a_sh[0][tid] = a_cur;

    float logscale = 0.f;

    float eb[4];
    #pragma unroll
    for (int jj = 0; jj < 4; jj++) eb[jj] = lg[(1 + jj) * NC + cc];
    __syncthreads();

    int p = 0;

    #define CRF_STEP(T, EMIS)                                                  \
    {                                                                          \
        float ex = __expf(EMIS);                                               \
        float r  = a_sh[p][0];                                                 \
        unsigned long long s0 = 0ull, s1 = 0ull, s2 = 0ull, s3 = 0ull;         \
        _Pragma("unroll")                                                      \
        for (int j = 0; j < 12; j += 2) {                                      \
            ulonglong2 u = *(const ulonglong2*)&a_sh[p][4 * j];                \
            ulonglong2 v = *(const ulonglong2*)&a_sh[p][4 * j + 4];            \
            s0 = ffma2(u.x, Ec2[2 * j],     s0);                               \
            s1 = ffma2(u.y, Ec2[2 * j + 1], s1);                               \
            s2 = ffma2(v.x, Ec2[2 * j + 2], s2);                               \
            s3 = ffma2(v.y, Ec2[2 * j + 3], s3);                               \
        }                                                                      \
        float2 sp = unpack2(fadd2(fadd2(s0, s2), fadd2(s1, s3)));              \
        float s = sp.x + sp.y;                                                 \
        bool rn = ((T) & 127) == 0;                                            \
        float sel = rn ? frcp_fast(r) : 1.0f;                                  \
        logscale += rn ? __logf(r) : 0.0f;                                     \
        float anew = s * ex * sel;                                             \
        a_sh[p ^ 1][tid] = anew;                                               \
        a_cur = anew;                                                          \
        __syncthreads();                                                       \
        p ^= 1;                                                                \
    }

    for (int tb = 1; tb + 3 < NT; tb += 4) {
        float en[4];
        #pragma unroll
        for (int jj = 0; jj < 4; jj++) {
            int tt = tb + 4 + jj;
            tt = (tt < NT) ? tt : (NT - 1);
            en[jj] = lg[tt * NC + cc];
        }
        CRF_STEP(tb + 0, eb[0]);
        CRF_STEP(tb + 1, eb[1]);
        CRF_STEP(tb + 2, eb[2]);
        CRF_STEP(tb + 3, eb[3]);
        eb[0] = en[0]; eb[1] = en[1]; eb[2] = en[2]; eb[3] = en[3];
    }
    CRF_STEP(NT - 3, eb[0]);
    CRF_STEP(NT - 2, eb[1]);
    CRF_STEP(NT - 1, eb[2]);
    #undef CRF_STEP

    // ---- logZ + per-chain partial; last block reduces everything ----
    if (tid < NC) red[tid] = a_cur * __expf(end_trans[tid]);
    __syncthreads();
    if (tid == 0) {
        float s = 0.f;
        #pragma unroll
        for (int i = 0; i < NC; i++) s += red[i];
        float logz = __logf(s) + logscale + 4254.5374f;   // + 1023*ln(64)
        g_partial[b] = num - logz;
        __threadfence();
        int v = atomicAdd(&g_done, 1);
        if (v == NB - 1) {                 // last chain: final reduce
            float tot = 0.f;
            #pragma unroll
            for (int i = 0; i < NB; i++) tot += g_partial[i];
            out[out_size - 1] = -tot;
            atomicExch(&g_done, 0);        // reset for graph replay
        }
    }
}

extern "C" void kernel_launch(void* const* d_in, const int* in_sizes, int n_in,
                              void* d_out, int out_size)
{
    const int*   x    = (const int*)  d_in[0];
    const int*   lab  = (const int*)  d_in[1];
    const float* emb  = (const float*)d_in[2];
    const float* fcw  = (const float*)d_in[3];
    const float* fcb  = (const float*)d_in[4];
    const float* st   = (const float*)d_in[5];
    const float* et   = (const float*)d_in[6];
    const float* tr   = (const float*)d_in[7];
    float* out = (float*)d_out;

    cudaFuncSetAttribute(gemm_kernel, cudaFuncAttributeMaxDynamicSharedMemorySize, GEMM_SMEM);
    gemm_kernel<<<NBLK, 128, GEMM_SMEM>>>(x, emb, fcw, fcb, out);
    crf_kernel<<<NB, 64>>>(out, lab, st, et, tr, out, out_size);
}